// round 6
// baseline (speedup 1.0000x reference)
#include <cuda_runtime.h>
#include <cuda_bf16.h>

#define FULLMASK 0xffffffffu
typedef unsigned long long u64;

// Two batch elements per warp.
// amp index (8 bits) per element: lane bits L0..L3 (lane&15) = qubits q0,q2,q4,q6
//                                  register bits j0..j3      = qubits q3,q5,q7,q1
// lane bit 4 = element selector. 16 u64 amplitudes per lane (packed re,im).
// Gate position codes: 0..3 = register bit, 4..7 = lane bit (code-4).

__device__ __forceinline__ u64 pk(float lo, float hi) {
    u64 r; asm("mov.b64 %0, {%1, %2};" : "=l"(r) : "f"(lo), "f"(hi)); return r;
}
__device__ __forceinline__ void upk(u64 v, float& x, float& y) {
    asm("mov.b64 {%0, %1}, %2;" : "=f"(x), "=f"(y) : "l"(v));
}
__device__ __forceinline__ u64 f2mul(u64 a, u64 b) {
    u64 r; asm("mul.rn.f32x2 %0, %1, %2;" : "=l"(r) : "l"(a), "l"(b)); return r;
}
__device__ __forceinline__ u64 f2fma(u64 a, u64 b, u64 c) {
    u64 r; asm("fma.rn.f32x2 %0, %1, %2, %3;" : "=l"(r) : "l"(a), "l"(b), "l"(c)); return r;
}
__device__ __forceinline__ u64 f2add(u64 a, u64 b) {
    u64 r; asm("add.rn.f32x2 %0, %1, %2;" : "=l"(r) : "l"(a), "l"(b)); return r;
}
__device__ __forceinline__ u64 swp(u64 v) { float x, y; upk(v, x, y); return pk(y, x); }
__device__ __forceinline__ u64 shx64(u64 v, int m) { return __shfl_xor_sync(FULLMASK, v, m); }
__device__ __forceinline__ u64 shxswp(u64 v, int m) {
    float x, y; upk(v, x, y);
    float sx = __shfl_xor_sync(FULLMASK, x, m);
    float sy = __shfl_xor_sync(FULLMASK, y, m);
    return pk(sy, sx);
}

// ---- Ry on position T (code): cc=(c,c), pp=(s,s), nn=(-s,-s) ----
template <int T>
__device__ __forceinline__ void applyRy(u64 s[16], u64 cc, u64 pp, u64 nn, int lane) {
    if constexpr (T < 4) {
        constexpr int m = 1 << T;
#pragma unroll
        for (int j = 0; j < 16; j++) {
            if (!(j & m)) {
                u64 a = s[j], b = s[j | m];
                s[j]     = f2fma(cc, a, f2mul(nn, b));
                s[j | m] = f2fma(cc, b, f2mul(pp, a));
            }
        }
    } else {
        constexpr int lb = 1 << (T - 4);
        u64 sg = (lane & lb) ? pp : nn;
#pragma unroll
        for (int j = 0; j < 16; j++) {
            u64 o = shx64(s[j], lb);
            s[j] = f2fma(cc, s[j], f2mul(sg, o));
        }
    }
}

// ---- controlled rotation: K=0 rx, K=1 ry, K=2 rz ----
// G[0]=(c,c) G[1]=(s,s) G[2]=(-s,-s) G[3]=(s,-s) G[4]=(-s,s)
template <int K, int Cb, int Tb>
__device__ __forceinline__ void applyCR(u64 s[16], const u64* __restrict__ G, int lane) {
    u64 cc = G[0];
    if constexpr (K == 2) {
        u64 pm = G[3], mp = G[4];
        bool laneT = (Tb >= 4) ? (((lane >> (Tb - 4)) & 1) != 0) : false;
        if constexpr (Cb < 4) {
#pragma unroll
            for (int j = 0; j < 16; j++) {
                if (j & (1 << Cb)) {
                    bool tb = (Tb < 4) ? (((j >> Tb) & 1) != 0) : laneT;
                    u64 f = tb ? mp : pm;
                    s[j] = f2fma(cc, s[j], f2mul(f, swp(s[j])));
                }
            }
        } else {
            bool lc = ((lane >> (Cb - 4)) & 1) != 0;
#pragma unroll
            for (int j = 0; j < 16; j++) {
                bool tb = (Tb < 4) ? (((j >> Tb) & 1) != 0) : laneT;
                u64 f = tb ? mp : pm;
                u64 r = f2fma(cc, s[j], f2mul(f, swp(s[j])));
                if (lc) s[j] = r;
            }
        }
    } else if constexpr (Tb < 4) {
        constexpr int tm = 1 << Tb;
        bool lc = (Cb >= 4) ? (((lane >> (Cb - 4)) & 1) != 0) : false;
#pragma unroll
        for (int j = 0; j < 16; j++) {
            if (!(j & tm) && (Cb >= 4 || ((j >> Cb) & 1))) {
                u64 a = s[j], b = s[j | tm], na, nb;
                if constexpr (K == 0) {   // rx
                    u64 pm = G[3];
                    na = f2fma(cc, a, f2mul(pm, swp(b)));
                    nb = f2fma(cc, b, f2mul(pm, swp(a)));
                } else {                  // ry
                    na = f2fma(cc, a, f2mul(G[2], b));
                    nb = f2fma(cc, b, f2mul(G[1], a));
                }
                if constexpr (Cb < 4) { s[j] = na; s[j | tm] = nb; }
                else { if (lc) { s[j] = na; s[j | tm] = nb; } }
            }
        }
    } else {
        constexpr int lb = 1 << (Tb - 4);
        u64 sg = (lane & lb) ? G[1] : G[2];
        if constexpr (Cb < 4) {
            // register control: shuffle only ctrl=1 slots, unconditional write
#pragma unroll
            for (int j = 0; j < 16; j++) {
                if (j & (1 << Cb)) {
                    if constexpr (K == 0) {
                        u64 os = shxswp(s[j], lb);
                        s[j] = f2fma(cc, s[j], f2mul(G[3], os));
                    } else {
                        u64 o = shx64(s[j], lb);
                        s[j] = f2fma(cc, s[j], f2mul(sg, o));
                    }
                }
            }
        } else {
            bool lc = ((lane >> (Cb - 4)) & 1) != 0;
#pragma unroll
            for (int j = 0; j < 16; j++) {
                u64 r;
                if constexpr (K == 0) r = f2fma(cc, s[j], f2mul(G[3], shxswp(s[j], lb)));
                else                  r = f2fma(cc, s[j], f2mul(sg, shx64(s[j], lb)));
                if (lc) s[j] = r;
            }
        }
    }
}

// ---- general u3 gate; U: u00r,u00i,u01r,u01i,u10r,u10i,u11r,u11i (uXr=(re,re), uXi=(-im,im)) ----
template <int Tb>
__device__ __forceinline__ void applyU3(u64 s[16], const u64* __restrict__ U, int lane) {
    if constexpr (Tb < 4) {
        constexpr int m = 1 << Tb;
#pragma unroll
        for (int j = 0; j < 16; j++) {
            if (!(j & m)) {
                u64 a = s[j], b = s[j | m];
                u64 as = swp(a), bs = swp(b);
                s[j]     = f2fma(U[0], a, f2fma(U[2], b, f2mul(U[3], bs)));
                s[j | m] = f2fma(U[4], a, f2fma(U[5], as, f2fma(U[6], b, f2mul(U[7], bs))));
            }
        }
    } else {
        constexpr int lb = 1 << (Tb - 4);
        bool hi = (lane & lb) != 0;
        u64 Ar = hi ? U[6] : U[0];
        u64 Ai = hi ? U[7] : U[1];
        u64 Br = hi ? U[4] : U[2];
        u64 Bi = hi ? U[5] : U[3];
#pragma unroll
        for (int j = 0; j < 16; j++) {
            float x, y; upk(s[j], x, y);
            float ox = __shfl_xor_sync(FULLMASK, x, lb);
            float oy = __shfl_xor_sync(FULLMASK, y, lb);
            u64 o = pk(ox, oy), os = pk(oy, ox), ss2 = pk(y, x);
            s[j] = f2fma(Ar, s[j], f2fma(Ai, ss2, f2fma(Br, o, f2mul(Bi, os))));
        }
    }
}

// ---- CNOT ----
template <int Cb, int Tb>
__device__ __forceinline__ void cnot(u64 s[16], int lane) {
    if constexpr (Tb < 4) {
        constexpr int tm = 1 << Tb;
        bool lc = (Cb >= 4) ? (((lane >> (Cb - 4)) & 1) != 0) : false;
#pragma unroll
        for (int j = 0; j < 16; j++) {
            if (!(j & tm)) {
                bool ctrl = (Cb < 4) ? (((j >> Cb) & 1) != 0) : lc;
                if (ctrl) { u64 t = s[j]; s[j] = s[j | tm]; s[j | tm] = t; }
            }
        }
    } else {
        constexpr int lb = 1 << (Tb - 4);
        if constexpr (Cb < 4) {
#pragma unroll
            for (int j = 0; j < 16; j++)
                if (j & (1 << Cb)) s[j] = shx64(s[j], lb);
        } else {
            bool lc = ((lane >> (Cb - 4)) & 1) != 0;
#pragma unroll
            for (int j = 0; j < 16; j++) {
                u64 o = shx64(s[j], lb);
                if (lc) s[j] = o;
            }
        }
    }
}

// CNOT ring: qubit codes q0=4,q1=3,q2=5,q3=0,q4=6,q5=1,q6=7,q7=2
__device__ __forceinline__ void ring_layer(u64 s[16], int lane) {
    cnot<4, 3>(s, lane);  // (q0,q1)
    cnot<3, 5>(s, lane);  // (q1,q2)
    cnot<5, 0>(s, lane);  // (q2,q3)
    cnot<0, 6>(s, lane);  // (q3,q4)
    cnot<6, 1>(s, lane);  // (q4,q5)
    cnot<1, 7>(s, lane);  // (q5,q6)
    cnot<7, 2>(s, lane);  // (q6,q7)
    cnot<2, 4>(s, lane);  // (q7,q0)
}

template <int K>
__device__ __forceinline__ void runBranch(u64 s[16], const u64* __restrict__ CR,
                                          const u64* __restrict__ UM,
                                          int lane, float& e3, float& e7) {
#define CRG(i, Cb, Tb) applyCR<K, Cb, Tb>(s, CR + (i) * 5, lane);
#define U3G(i, Tb) applyU3<Tb>(s, UM + (i) * 8, lane);
    // PAIRS_A (qubit pairs -> codes)
    CRG(0, 4, 3)  // (0,1)
    CRG(1, 5, 0)  // (2,3)
    CRG(2, 6, 1)  // (4,5)
    CRG(3, 7, 2)  // (6,7)
    CRG(4, 3, 5)  // (1,2)
    CRG(5, 0, 6)  // (3,4)
    CRG(6, 1, 7)  // (5,6)
    // u3 on wires 1,3,5,7 -> codes 3,0,1,2 (all register-local)
    U3G(0, 3) U3G(1, 0) U3G(2, 1) U3G(3, 2)
    // PAIRS_B (all register-local)
    CRG(7, 3, 0)  // (1,3)
    CRG(8, 1, 2)  // (5,7)
    CRG(9, 0, 1)  // (3,5)
    // u3 on wires 3,7 -> codes 0,2
    U3G(4, 0) U3G(5, 2)
#undef CRG
#undef U3G

    // expz(q3)=j bit0, expz(q7)=j bit2
    float q[16];
#pragma unroll
    for (int j = 0; j < 16; j++) {
        float x, y; upk(s[j], x, y);
        q[j] = x * x + y * y;
    }
    float a3 = 0.f, a7 = 0.f;
#pragma unroll
    for (int j = 0; j < 16; j++) {
        a3 += (j & 1) ? -q[j] : q[j];
        a7 += (j & 4) ? -q[j] : q[j];
    }
    // reduce over 4 lane bits (stays within each 16-lane half)
    u64 e = pk(a3, a7);
    e = f2add(e, shx64(e, 1));
    e = f2add(e, shx64(e, 2));
    e = f2add(e, shx64(e, 4));
    e = f2add(e, shx64(e, 8));
    upk(e, e3, e7);
}

__global__ __launch_bounds__(256) void qcnn_kernel(
    const float* __restrict__ theta, const float* __restrict__ phi,
    const float* __restrict__ angles_x, const float* __restrict__ angles_y,
    const float* __restrict__ angles_z,
    const float* __restrict__ u3_x, const float* __restrict__ u3_y,
    const float* __restrict__ u3_z,
    const float* __restrict__ W1, const float* __restrict__ b1,
    const float* __restrict__ W2, const float* __restrict__ b2,
    float* __restrict__ out, int B)
{
    __shared__ u64 shCR[3 * 10 * 5];   // packed (c,c),(s,s),(-s,-s),(s,-s),(-s,s)
    __shared__ u64 shU3[3 * 6 * 8];    // packed uXr/uXi
    __shared__ u64 shP0[8 * 512];      // psi0 snapshot: [warp][j][lane]
    __shared__ float shW1[72], shB1[12], shW2[12];
    __shared__ float shB2;

    int tid = threadIdx.x;
    if (tid < 30) {
        int b = tid / 10, i = tid % 10;
        const float* ang = (b == 0) ? angles_x : (b == 1) ? angles_y : angles_z;
        float sn, c;
        sincosf(0.5f * ang[i], &sn, &c);
        u64* g = &shCR[tid * 5];
        g[0] = pk(c, c);
        g[1] = pk(sn, sn);
        g[2] = pk(-sn, -sn);
        g[3] = pk(sn, -sn);
        g[4] = pk(-sn, sn);
    }
    if (tid >= 32 && tid < 50) {
        int k = tid - 32;
        int b = k / 6, i = k % 6;
        const float* up = ((b == 0) ? u3_x : (b == 1) ? u3_y : u3_z) + i * 3;
        float th = up[0], ph = up[1], lm = up[2];
        float sn, c;    sincosf(0.5f * th, &sn, &c);
        float sl, cl;   sincosf(lm, &sl, &cl);
        float sp, cp;   sincosf(ph, &sp, &cp);
        float spl, cpl; sincosf(ph + lm, &spl, &cpl);
        u64* g = &shU3[k * 8];
        g[0] = pk(c, c);                 g[1] = pk(0.f, 0.f);
        g[2] = pk(-cl * sn, -cl * sn);   g[3] = pk(sl * sn, -sl * sn);
        g[4] = pk(cp * sn, cp * sn);     g[5] = pk(-sp * sn, sp * sn);
        g[6] = pk(cpl * c, cpl * c);     g[7] = pk(-spl * c, spl * c);
    }
    if (tid >= 64 && tid < 136)  shW1[tid - 64] = W1[tid - 64];
    if (tid >= 136 && tid < 148) shB1[tid - 136] = b1[tid - 136];
    if (tid >= 148 && tid < 160) shW2[tid - 148] = W2[tid - 148];
    if (tid == 160) shB2 = b2[0];
    __syncthreads();

    int warp = tid >> 5;
    int lane = tid & 31;
    int elemBase = (blockIdx.x * 8 + warp) * 2;
    if (elemBase >= B) return;
    int elem = elemBase + (lane >> 4);

    float th = theta[elem];
    float ph = phi[elem];

    float sy, cy;
    sincosf(0.5f * th, &sy, &cy);
    u64 cc = pk(cy, cy), pp = pk(sy, sy), nn = pk(-sy, -sy);

    // Rz-layer combined diagonal: amp *= cis(ph * (popc(idx) - 4))
    // per-lane base phase from popc(lane&15); per-j extra by popc(j) (0..4)
    int pl = __popc(lane & 15);
    float c1x, c1y; sincosf(ph, &c1y, &c1x);
    float cl0x, cl0y; sincosf(ph * (float)(pl - 4), &cl0y, &cl0x);
    // packed phase rotators pr[d]=(x,x), pi[d]=(-y,y), d = popc(j) in 0..4
    u64 pr[5], pi[5];
    {
        float x = cl0x, y = cl0y;
#pragma unroll
        for (int d = 0; d < 5; d++) {
            pr[d] = pk(x, x);
            pi[d] = pk(-y, y);
            float nx = x * c1x - y * c1y;
            float ny = x * c1y + y * c1x;
            x = nx; y = ny;
        }
    }
    const int POPC[16] = {0,1,1,2,1,2,2,3,1,2,2,3,2,3,3,4};

    // ---- cycle 1: closed-form product state ----
    u64 s[16];
    {
        float base = 1.f;
#pragma unroll
        for (int k = 0; k < 4; k++) base *= ((lane >> k) & 1) ? sy : cy;
        float f[5];
        f[0] = cy * cy * cy * cy;
        f[1] = cy * cy * cy * sy;
        f[2] = cy * cy * sy * sy;
        f[3] = cy * sy * sy * sy;
        f[4] = sy * sy * sy * sy;
#pragma unroll
        for (int j = 0; j < 16; j++) {
            int d = POPC[j];
            float w = base * f[d];
            float x, y0; upk(pr[d], x, y0);
            float ix, iy; upk(pi[d], ix, iy);
            // amplitude = w * (cos, sin) ; pr holds (cos,cos), pi holds (-sin,sin)
            s[j] = pk(x * w, iy * w);
        }
    }
    ring_layer(s, lane);

    // ---- cycles 2..4 ----
#pragma unroll 1
    for (int cyc = 0; cyc < 3; cyc++) {
        applyRy<0>(s, cc, pp, nn, lane);
        applyRy<1>(s, cc, pp, nn, lane);
        applyRy<2>(s, cc, pp, nn, lane);
        applyRy<3>(s, cc, pp, nn, lane);
        applyRy<4>(s, cc, pp, nn, lane);
        applyRy<5>(s, cc, pp, nn, lane);
        applyRy<6>(s, cc, pp, nn, lane);
        applyRy<7>(s, cc, pp, nn, lane);
        // phase multiply: s[j] *= cis(...) packed: fma(pr, s, mul(pi, swap(s)))
#pragma unroll
        for (int j = 0; j < 16; j++) {
            int d = POPC[j];
            s[j] = f2fma(pr[d], s[j], f2mul(pi[d], swp(s[j])));
        }
        ring_layer(s, lane);
    }

    // ---- save psi0 to shared ----
    u64* myP0 = &shP0[warp * 512 + lane];
#pragma unroll
    for (int j = 0; j < 16; j++) myP0[j * 32] = s[j];

    float feats[6];

    runBranch<0>(s, &shCR[0],   &shU3[0],  lane, feats[0], feats[1]);
#pragma unroll
    for (int j = 0; j < 16; j++) s[j] = myP0[j * 32];
    runBranch<1>(s, &shCR[50],  &shU3[48], lane, feats[2], feats[3]);
#pragma unroll
    for (int j = 0; j < 16; j++) s[j] = myP0[j * 32];
    runBranch<2>(s, &shCR[100], &shU3[96], lane, feats[4], feats[5]);

    // ---- MLP (one lane per element) ----
    if ((lane & 15) == 0) {
        float h[12];
#pragma unroll
        for (int k = 0; k < 12; k++) {
            float a = shB1[k];
#pragma unroll
            for (int f = 0; f < 6; f++) a += shW1[k * 6 + f] * feats[f];
            h[k] = tanhf(a);
        }
        float o = shB2;
#pragma unroll
        for (int k = 0; k < 12; k++) o += shW2[k] * h[k];
        out[elem] = 1.f / (1.f + expf(-o));
    }
}

extern "C" void kernel_launch(void* const* d_in, const int* in_sizes, int n_in,
                              void* d_out, int out_size) {
    const float* theta    = (const float*)d_in[0];
    const float* phi      = (const float*)d_in[1];
    const float* angles_x = (const float*)d_in[2];
    const float* angles_y = (const float*)d_in[3];
    const float* angles_z = (const float*)d_in[4];
    const float* u3_x     = (const float*)d_in[5];
    const float* u3_y     = (const float*)d_in[6];
    const float* u3_z     = (const float*)d_in[7];
    const float* W1       = (const float*)d_in[8];
    const float* b1       = (const float*)d_in[9];
    const float* W2       = (const float*)d_in[10];
    const float* b2       = (const float*)d_in[11];
    float* out = (float*)d_out;

    int B = in_sizes[0];
    int blocks = (B + 15) / 16;
    qcnn_kernel<<<blocks, 256>>>(theta, phi, angles_x, angles_y, angles_z,
                                 u3_x, u3_y, u3_z, W1, b1, W2, b2, out, B);
}

// round 8
// speedup vs baseline: 1.2366x; 1.2366x over previous
#include <cuda_runtime.h>
#include <cuda_bf16.h>

#define FULLMASK 0xffffffffu
typedef unsigned long long u64;

// Qubit -> amplitude-index-bit mapping (R4 layout):
//   q3->bit0, q5->bit1, q7->bit2  (register bits: j index 0..7)
//   q0->bit3(L0), q1->bit4(L1), q2->bit5(L2), q4->bit6(L3), q6->bit7(L4)
// amp index = (lane << 3) | j ; amplitude = packed (re, im) in one 64-bit pair

__device__ __forceinline__ u64 pk(float lo, float hi) {
    u64 r; asm("mov.b64 %0, {%1, %2};" : "=l"(r) : "f"(lo), "f"(hi)); return r;
}
__device__ __forceinline__ void upk(u64 v, float& x, float& y) {
    asm("mov.b64 {%0, %1}, %2;" : "=f"(x), "=f"(y) : "l"(v));
}
__device__ __forceinline__ u64 f2mul(u64 a, u64 b) {
    u64 r; asm("mul.rn.f32x2 %0, %1, %2;" : "=l"(r) : "l"(a), "l"(b)); return r;
}
__device__ __forceinline__ u64 f2fma(u64 a, u64 b, u64 c) {
    u64 r; asm("fma.rn.f32x2 %0, %1, %2, %3;" : "=l"(r) : "l"(a), "l"(b), "l"(c)); return r;
}
__device__ __forceinline__ u64 f2add(u64 a, u64 b) {
    u64 r; asm("add.rn.f32x2 %0, %1, %2;" : "=l"(r) : "l"(a), "l"(b)); return r;
}
__device__ __forceinline__ u64 swp(u64 v) { float x, y; upk(v, x, y); return pk(y, x); }
__device__ __forceinline__ u64 shx64(u64 v, int m) { return __shfl_xor_sync(FULLMASK, v, m); }
__device__ __forceinline__ u64 shxswp(u64 v, int m) {
    float x, y; upk(v, x, y);
    float sx = __shfl_xor_sync(FULLMASK, x, m);
    float sy = __shfl_xor_sync(FULLMASK, y, m);
    return pk(sy, sx);
}

// ---- Ry on index-bit Tb ----
template <int Tb>
__device__ __forceinline__ void applyRy(u64 s[8], u64 cc, u64 pp, u64 nn, int lane) {
    if constexpr (Tb < 3) {
        constexpr int m = 1 << Tb;
#pragma unroll
        for (int j = 0; j < 8; j++) {
            if (!(j & m)) {
                u64 a = s[j], b = s[j | m];
                s[j]     = f2fma(cc, a, f2mul(nn, b));
                s[j | m] = f2fma(cc, b, f2mul(pp, a));
            }
        }
    } else {
        constexpr int lb = 1 << (Tb - 3);
        u64 sg = (lane & lb) ? pp : nn;
#pragma unroll
        for (int j = 0; j < 8; j++) {
            u64 o = shx64(s[j], lb);
            s[j] = f2fma(cc, s[j], f2mul(sg, o));
        }
    }
}

// ---- controlled rotation: K=0 rx, K=1 ry, K=2 rz ----
// G[0]=(c,c) G[1]=(s,s) G[2]=(-s,-s) G[3]=(s,-s) G[4]=(-s,s)
template <int K, int Cb, int Tb>
__device__ __forceinline__ void applyCR(u64 s[8], const u64* __restrict__ G, int lane) {
    u64 cc = G[0];
    if constexpr (K == 2) {
        u64 pm = G[3], mp = G[4];
        bool laneT = (Tb >= 3) ? (((lane >> (Tb - 3)) & 1) != 0) : false;
        if constexpr (Cb < 3) {
#pragma unroll
            for (int j = 0; j < 8; j++) {
                if (j & (1 << Cb)) {
                    bool tb = (Tb < 3) ? (((j >> Tb) & 1) != 0) : laneT;
                    u64 f = tb ? mp : pm;
                    s[j] = f2fma(cc, s[j], f2mul(f, swp(s[j])));
                }
            }
        } else {
            bool lc = ((lane >> (Cb - 3)) & 1) != 0;
#pragma unroll
            for (int j = 0; j < 8; j++) {
                bool tb = (Tb < 3) ? (((j >> Tb) & 1) != 0) : laneT;
                u64 f = tb ? mp : pm;
                u64 r = f2fma(cc, s[j], f2mul(f, swp(s[j])));
                if (lc) s[j] = r;
            }
        }
    } else if constexpr (Tb < 3) {
        constexpr int tm = 1 << Tb;
        bool lc = (Cb >= 3) ? (((lane >> (Cb - 3)) & 1) != 0) : false;
#pragma unroll
        for (int j = 0; j < 8; j++) {
            if (!(j & tm) && (Cb >= 3 || ((j >> Cb) & 1))) {
                u64 a = s[j], b = s[j | tm], na, nb;
                if constexpr (K == 0) {   // rx
                    u64 pm = G[3];
                    na = f2fma(cc, a, f2mul(pm, swp(b)));
                    nb = f2fma(cc, b, f2mul(pm, swp(a)));
                } else {                  // ry
                    na = f2fma(cc, a, f2mul(G[2], b));
                    nb = f2fma(cc, b, f2mul(G[1], a));
                }
                if constexpr (Cb < 3) { s[j] = na; s[j | tm] = nb; }
                else { if (lc) { s[j] = na; s[j | tm] = nb; } }
            }
        }
    } else {
        constexpr int lb = 1 << (Tb - 3);
        u64 sg = (lane & lb) ? G[1] : G[2];
        if constexpr (Cb < 3) {
#pragma unroll
            for (int j = 0; j < 8; j++) {
                if (j & (1 << Cb)) {
                    if constexpr (K == 0) {
                        u64 os = shxswp(s[j], lb);
                        s[j] = f2fma(cc, s[j], f2mul(G[3], os));
                    } else {
                        u64 o = shx64(s[j], lb);
                        s[j] = f2fma(cc, s[j], f2mul(sg, o));
                    }
                }
            }
        } else {
            bool lc = ((lane >> (Cb - 3)) & 1) != 0;
#pragma unroll
            for (int j = 0; j < 8; j++) {
                u64 r;
                if constexpr (K == 0) r = f2fma(cc, s[j], f2mul(G[3], shxswp(s[j], lb)));
                else                  r = f2fma(cc, s[j], f2mul(sg, shx64(s[j], lb)));
                if (lc) s[j] = r;
            }
        }
    }
}

// ---- general u3 gate; U: u00r,u00i,u01r,u01i,u10r,u10i,u11r,u11i (uXr=(re,re), uXi=(-im,im)) ----
template <int Tb>
__device__ __forceinline__ void applyU3(u64 s[8], const u64* __restrict__ U, int lane) {
    if constexpr (Tb < 3) {
        constexpr int m = 1 << Tb;
#pragma unroll
        for (int j = 0; j < 8; j++) {
            if (!(j & m)) {
                u64 a = s[j], b = s[j | m];
                u64 as = swp(a), bs = swp(b);
                s[j]     = f2fma(U[0], a, f2fma(U[2], b, f2mul(U[3], bs)));
                s[j | m] = f2fma(U[4], a, f2fma(U[5], as, f2fma(U[6], b, f2mul(U[7], bs))));
            }
        }
    } else {
        constexpr int lb = 1 << (Tb - 3);
        bool hi = (lane & lb) != 0;
        u64 Ar = hi ? U[6] : U[0];
        u64 Ai = hi ? U[7] : U[1];
        u64 Br = hi ? U[4] : U[2];
        u64 Bi = hi ? U[5] : U[3];
#pragma unroll
        for (int j = 0; j < 8; j++) {
            float x, y; upk(s[j], x, y);
            float ox = __shfl_xor_sync(FULLMASK, x, lb);
            float oy = __shfl_xor_sync(FULLMASK, y, lb);
            u64 o = pk(ox, oy), os = pk(oy, ox), ss2 = pk(y, x);
            s[j] = f2fma(Ar, s[j], f2fma(Ai, ss2, f2fma(Br, o, f2mul(Bi, os))));
        }
    }
}

// ---- CNOT ----
template <int Cb, int Tb>
__device__ __forceinline__ void cnot(u64 s[8], int lane) {
    if constexpr (Tb < 3) {
        constexpr int tm = 1 << Tb;
        bool lc = (Cb >= 3) ? (((lane >> (Cb - 3)) & 1) != 0) : false;
#pragma unroll
        for (int j = 0; j < 8; j++) {
            if (!(j & tm)) {
                bool ctrl = (Cb < 3) ? (((j >> Cb) & 1) != 0) : lc;
                if (ctrl) { u64 t = s[j]; s[j] = s[j | tm]; s[j | tm] = t; }
            }
        }
    } else {
        constexpr int lb = 1 << (Tb - 3);
        if constexpr (Cb < 3) {
#pragma unroll
            for (int j = 0; j < 8; j++)
                if (j & (1 << Cb)) s[j] = shx64(s[j], lb);
        } else {
            bool lc = ((lane >> (Cb - 3)) & 1) != 0;
#pragma unroll
            for (int j = 0; j < 8; j++) {
                u64 o = shx64(s[j], lb);
                if (lc) s[j] = o;
            }
        }
    }
}

// fused cnot<3,4>; cnot<4,5> — pure lane permutation, one gather shuffle
__device__ __forceinline__ void ring_head(u64 s[8], int lane) {
    int src = lane ^ (((lane >> 1) & 1) << 2) ^ ((lane & 1) << 1);
#pragma unroll
    for (int j = 0; j < 8; j++) s[j] = __shfl_sync(FULLMASK, s[j], src);
}

__device__ __forceinline__ void ring_layer(u64 s[8], int lane) {
    ring_head(s, lane);   // (q0,q1), (q1,q2)
    cnot<5, 0>(s, lane);  // (q2,q3)
    cnot<0, 6>(s, lane);  // (q3,q4)
    cnot<6, 1>(s, lane);  // (q4,q5)
    cnot<1, 7>(s, lane);  // (q5,q6)
    cnot<7, 2>(s, lane);  // (q6,q7)
    cnot<2, 3>(s, lane);  // (q7,q0)
}

// interleaved x (K=0) and y (K=1) branches for ILP
__device__ __forceinline__ void runBranchXY(u64 sx[8], u64 sy[8],
                                            const u64* __restrict__ CRx,
                                            const u64* __restrict__ CRy,
                                            const u64* __restrict__ UMx,
                                            const u64* __restrict__ UMy,
                                            int lane, float* feats) {
#define CRG2(i, Cb, Tb) { applyCR<0, Cb, Tb>(sx, CRx + (i) * 5, lane); \
                          applyCR<1, Cb, Tb>(sy, CRy + (i) * 5, lane); }
#define U3G2(i, Tb) { applyU3<Tb>(sx, UMx + (i) * 8, lane); \
                      applyU3<Tb>(sy, UMy + (i) * 8, lane); }
    // PAIRS_A
    CRG2(0, 3, 4)  // (0,1)
    CRG2(1, 5, 0)  // (2,3)
    CRG2(2, 6, 1)  // (4,5)
    CRG2(3, 7, 2)  // (6,7)
    CRG2(4, 4, 5)  // (1,2)
    CRG2(5, 0, 6)  // (3,4)
    CRG2(6, 1, 7)  // (5,6)
    // u3 on wires 1,3,5,7 -> bits 4,0,1,2
    U3G2(0, 4) U3G2(1, 0) U3G2(2, 1) U3G2(3, 2)
    // PAIRS_B
    CRG2(7, 4, 0)  // (1,3)
    CRG2(8, 1, 2)  // (5,7)
    CRG2(9, 0, 1)  // (3,5)
    // u3 on wires 3,7 -> bits 0,2
    U3G2(4, 0) U3G2(5, 2)
#undef CRG2
#undef U3G2

    float qx[8], qy[8];
#pragma unroll
    for (int j = 0; j < 8; j++) {
        float x, y; upk(sx[j], x, y); qx[j] = x * x + y * y;
        float x2, y2; upk(sy[j], x2, y2); qy[j] = x2 * x2 + y2 * y2;
    }
    float a3x = 0.f, a7x = 0.f, a3y = 0.f, a7y = 0.f;
#pragma unroll
    for (int j = 0; j < 8; j++) {
        a3x += (j & 1) ? -qx[j] : qx[j];
        a7x += (j & 4) ? -qx[j] : qx[j];
        a3y += (j & 1) ? -qy[j] : qy[j];
        a7y += (j & 4) ? -qy[j] : qy[j];
    }
    u64 ex = pk(a3x, a7x), ey = pk(a3y, a7y);
#pragma unroll
    for (int o = 16; o > 0; o >>= 1) {
        ex = f2add(ex, shx64(ex, o));
        ey = f2add(ey, shx64(ey, o));
    }
    upk(ex, feats[0], feats[1]);
    upk(ey, feats[2], feats[3]);
}

// z branch alone (cheap: CRz diagonal, u3 mostly register-local)
__device__ __forceinline__ void runBranchZ(u64 s[8], const u64* __restrict__ CR,
                                           const u64* __restrict__ UM,
                                           int lane, float& e3, float& e7) {
#define CRG(i, Cb, Tb) applyCR<2, Cb, Tb>(s, CR + (i) * 5, lane);
#define U3G(i, Tb) applyU3<Tb>(s, UM + (i) * 8, lane);
    CRG(0, 3, 4) CRG(1, 5, 0) CRG(2, 6, 1) CRG(3, 7, 2)
    CRG(4, 4, 5) CRG(5, 0, 6) CRG(6, 1, 7)
    U3G(0, 4) U3G(1, 0) U3G(2, 1) U3G(3, 2)
    CRG(7, 4, 0) CRG(8, 1, 2) CRG(9, 0, 1)
    U3G(4, 0) U3G(5, 2)
#undef CRG
#undef U3G
    float q[8];
#pragma unroll
    for (int j = 0; j < 8; j++) {
        float x, y; upk(s[j], x, y);
        q[j] = x * x + y * y;
    }
    float a3 = 0.f, a7 = 0.f;
#pragma unroll
    for (int j = 0; j < 8; j++) {
        a3 += (j & 1) ? -q[j] : q[j];
        a7 += (j & 4) ? -q[j] : q[j];
    }
    u64 e = pk(a3, a7);
#pragma unroll
    for (int o = 16; o > 0; o >>= 1) e = f2add(e, shx64(e, o));
    upk(e, e3, e7);
}

__global__ __launch_bounds__(256) void qcnn_kernel(
    const float* __restrict__ theta, const float* __restrict__ phi,
    const float* __restrict__ angles_x, const float* __restrict__ angles_y,
    const float* __restrict__ angles_z,
    const float* __restrict__ u3_x, const float* __restrict__ u3_y,
    const float* __restrict__ u3_z,
    const float* __restrict__ W1, const float* __restrict__ b1,
    const float* __restrict__ W2, const float* __restrict__ b2,
    float* __restrict__ out, int B)
{
    __shared__ u64 shCR[3 * 10 * 5];
    __shared__ u64 shU3[3 * 6 * 8];
    __shared__ u64 shP0[8 * 256];      // psi0 snapshot: [warp][j][lane]
    __shared__ float shW1[72], shB1[12], shW2[12];
    __shared__ float shB2;

    int tid = threadIdx.x;
    if (tid < 30) {
        int b = tid / 10, i = tid % 10;
        const float* ang = (b == 0) ? angles_x : (b == 1) ? angles_y : angles_z;
        float sn, c;
        sincosf(0.5f * ang[i], &sn, &c);
        u64* g = &shCR[tid * 5];
        g[0] = pk(c, c);
        g[1] = pk(sn, sn);
        g[2] = pk(-sn, -sn);
        g[3] = pk(sn, -sn);
        g[4] = pk(-sn, sn);
    }
    if (tid >= 32 && tid < 50) {
        int k = tid - 32;
        int b = k / 6, i = k % 6;
        const float* up = ((b == 0) ? u3_x : (b == 1) ? u3_y : u3_z) + i * 3;
        float th = up[0], ph = up[1], lm = up[2];
        float sn, c;    sincosf(0.5f * th, &sn, &c);
        float sl, cl;   sincosf(lm, &sl, &cl);
        float sp, cp;   sincosf(ph, &sp, &cp);
        float spl, cpl; sincosf(ph + lm, &spl, &cpl);
        u64* g = &shU3[k * 8];
        g[0] = pk(c, c);                 g[1] = pk(0.f, 0.f);
        g[2] = pk(-cl * sn, -cl * sn);   g[3] = pk(sl * sn, -sl * sn);
        g[4] = pk(cp * sn, cp * sn);     g[5] = pk(-sp * sn, sp * sn);
        g[6] = pk(cpl * c, cpl * c);     g[7] = pk(-spl * c, spl * c);
    }
    if (tid >= 64 && tid < 136)  shW1[tid - 64] = W1[tid - 64];
    if (tid >= 136 && tid < 148) shB1[tid - 136] = b1[tid - 136];
    if (tid >= 148 && tid < 160) shW2[tid - 148] = W2[tid - 148];
    if (tid == 160) shB2 = b2[0];
    __syncthreads();

    int warp = tid >> 5;
    int lane = tid & 31;
    int batch = blockIdx.x * 8 + warp;
    if (batch >= B) return;

    float th = theta[batch];
    float ph = phi[batch];

    float sy, cy;
    sincosf(0.5f * th, &sy, &cy);
    u64 cc = pk(cy, cy), pp = pk(sy, sy), nn = pk(-sy, -sy);

    // Rz-layer combined diagonal: amp *= cis(ph * (popcount(idx) - 4))
    float c1x, c1y; sincosf(ph, &c1y, &c1x);
    float cl0x, cl0y; sincosf(ph * (float)(__popc(lane) - 4), &cl0y, &cl0x);
    float px[4], py[4];
    px[0] = cl0x; py[0] = cl0y;
    px[1] = px[0] * c1x - py[0] * c1y; py[1] = px[0] * c1y + py[0] * c1x;
    px[2] = px[1] * c1x - py[1] * c1y; py[2] = px[1] * c1y + py[1] * c1x;
    px[3] = px[2] * c1x - py[2] * c1y; py[3] = px[2] * c1y + py[2] * c1x;
    const int POPC[8] = {0, 1, 1, 2, 1, 2, 2, 3};

    // ---- cycle 1: closed form product state ----
    u64 s[8];
    {
        float base = 1.f;
#pragma unroll
        for (int k = 0; k < 5; k++) base *= ((lane >> k) & 1) ? sy : cy;
        float f0 = cy * cy * cy;
        float f1 = cy * cy * sy;
        float f2 = cy * sy * sy;
        float f3 = sy * sy * sy;
        float fj[8] = {f0, f1, f1, f2, f1, f2, f2, f3};
#pragma unroll
        for (int j = 0; j < 8; j++) {
            float w = base * fj[j];
            int d = POPC[j];
            s[j] = pk(px[d] * w, py[d] * w);
        }
    }
    ring_layer(s, lane);

    // ---- cycles 2..4: Ry layer with lane/register gates interleaved ----
#pragma unroll 1
    for (int cyc = 0; cyc < 3; cyc++) {
        applyRy<3>(s, cc, pp, nn, lane);
        applyRy<0>(s, cc, pp, nn, lane);
        applyRy<4>(s, cc, pp, nn, lane);
        applyRy<1>(s, cc, pp, nn, lane);
        applyRy<5>(s, cc, pp, nn, lane);
        applyRy<2>(s, cc, pp, nn, lane);
        applyRy<6>(s, cc, pp, nn, lane);
        applyRy<7>(s, cc, pp, nn, lane);
#pragma unroll
        for (int j = 0; j < 8; j++) {
            float x, y; upk(s[j], x, y);
            int d = POPC[j];
            s[j] = pk(px[d] * x - py[d] * y, px[d] * y + py[d] * x);
        }
        ring_layer(s, lane);
    }

    // ---- save psi0 to shared (only needed again for z branch) ----
    u64* myP0 = &shP0[warp * 256 + lane];
#pragma unroll
    for (int j = 0; j < 8; j++) myP0[j * 32] = s[j];

    float feats[6];

    // interleaved x + y branches (double ILP)
    {
        u64 s2[8];
#pragma unroll
        for (int j = 0; j < 8; j++) s2[j] = s[j];
        runBranchXY(s, s2, &shCR[0], &shCR[50], &shU3[0], &shU3[48], lane, feats);
    }

    // z branch
#pragma unroll
    for (int j = 0; j < 8; j++) s[j] = myP0[j * 32];
    runBranchZ(s, &shCR[100], &shU3[96], lane, feats[4], feats[5]);

    // ---- MLP (lane 0 only) ----
    if (lane == 0) {
        float h[12];
#pragma unroll
        for (int k = 0; k < 12; k++) {
            float a = shB1[k];
#pragma unroll
            for (int f = 0; f < 6; f++) a += shW1[k * 6 + f] * feats[f];
            h[k] = tanhf(a);
        }
        float o = shB2;
#pragma unroll
        for (int k = 0; k < 12; k++) o += shW2[k] * h[k];
        out[batch] = 1.f / (1.f + expf(-o));
    }
}

extern "C" void kernel_launch(void* const* d_in, const int* in_sizes, int n_in,
                              void* d_out, int out_size) {
    const float* theta    = (const float*)d_in[0];
    const float* phi      = (const float*)d_in[1];
    const float* angles_x = (const float*)d_in[2];
    const float* angles_y = (const float*)d_in[3];
    const float* angles_z = (const float*)d_in[4];
    const float* u3_x     = (const float*)d_in[5];
    const float* u3_y     = (const float*)d_in[6];
    const float* u3_z     = (const float*)d_in[7];
    const float* W1       = (const float*)d_in[8];
    const float* b1       = (const float*)d_in[9];
    const float* W2       = (const float*)d_in[10];
    const float* b2       = (const float*)d_in[11];
    float* out = (float*)d_out;

    int B = in_sizes[0];
    int blocks = (B + 7) / 8;
    qcnn_kernel<<<blocks, 256>>>(theta, phi, angles_x, angles_y, angles_z,
                                 u3_x, u3_y, u3_z, W1, b1, W2, b2, out, B);
}